// round 8
// baseline (speedup 1.0000x reference)
#include <cuda_runtime.h>
#include <cuda_bf16.h>
#include <cstdint>

// Problem constants: B=16, H=16, M=256, N=576, D=1024
#define BB 16
#define HH 16
#define MM 256
#define NN 576
#define DD 1024

#define EPSF 1e-8f
#define MU_C (1.0f / 576.0f)
#define FI_C (1.0f / 1.1f)

// ---------------- device scratch ----------------
__device__ __nv_bfloat16 g_xb[BB * NN * DD];   // visual feats bf16 (raw)
__device__ __nv_bfloat16 g_yb[BB * MM * DD];   // text feats bf16 (raw)
__device__ float g_inv_nx[BB * NN];
__device__ float g_inv_ny[BB * MM];
__device__ float g_K[BB * MM * NN];            // K, then overwritten with P*mask
__device__ float g_LS[BB * MM * NN];           // sum_h log(student)
__device__ float g_vpart[2][8][BB * NN];       // per-rank partial Ktu (parity buffered)
__device__ float g_partial[BB * MM];
__device__ unsigned g_done;

// ---------------- helpers ----------------
__device__ __forceinline__ float warp_sum(float v) {
#pragma unroll
    for (int o = 16; o; o >>= 1) v += __shfl_xor_sync(0xffffffffu, v, o);
    return v;
}

__device__ __forceinline__ float block_sum256(float v, volatile float* red) {
    int tid = threadIdx.x;
    float w = warp_sum(v);
    if ((tid & 31) == 0) red[tid >> 5] = w;
    __syncthreads();
    if (tid < 32) {
        float r = (tid < 8) ? red[tid] : 0.0f;
        r = warp_sum(r);
        if (tid == 0) red[0] = r;
    }
    __syncthreads();
    float out = red[0];
    __syncthreads();
    return out;
}

__device__ __forceinline__ float block_sum288(float v, volatile float* red) {
    int tid = threadIdx.x;
    float w = warp_sum(v);
    if ((tid & 31) == 0) red[tid >> 5] = w;
    __syncthreads();
    if (tid < 32) {
        float r = (tid < 9) ? red[tid] : 0.0f;
        r = warp_sum(r);
        if (tid == 0) red[0] = r;
    }
    __syncthreads();
    return red[0];
}

__device__ __forceinline__ void cluster_sync() {
    asm volatile("barrier.cluster.arrive.aligned;" ::: "memory");
    asm volatile("barrier.cluster.wait.aligned;" ::: "memory");
}

__device__ __forceinline__ void ldsm4(uint32_t* r, uint32_t addr) {
    asm volatile("ldmatrix.sync.aligned.m8n8.x4.shared.b16 {%0,%1,%2,%3}, [%4];"
                 : "=r"(r[0]), "=r"(r[1]), "=r"(r[2]), "=r"(r[3]) : "r"(addr));
}

__device__ __forceinline__ void mma16816(float* c, const uint32_t* a, const uint32_t* b) {
    asm volatile(
        "mma.sync.aligned.m16n8k16.row.col.f32.bf16.bf16.f32 "
        "{%0,%1,%2,%3}, {%4,%5,%6,%7}, {%8,%9}, {%0,%1,%2,%3};"
        : "+f"(c[0]), "+f"(c[1]), "+f"(c[2]), "+f"(c[3])
        : "r"(a[0]), "r"(a[1]), "r"(a[2]), "r"(a[3]), "r"(b[0]), "r"(b[1]));
}

__device__ __forceinline__ void cp16(uint32_t dst, const void* src) {
    asm volatile("cp.async.cg.shared.global [%0], [%1], 16;" :: "r"(dst), "l"(src));
}

// ---------------- kernel 1: norms + bf16 conversion ----------------
__global__ void __launch_bounds__(256) prep_kernel(const float* __restrict__ visual,
                                                   const float* __restrict__ text) {
    int warp = blockIdx.x * 8 + (threadIdx.x >> 5);
    int lane = threadIdx.x & 31;
    const int VROWS = BB * NN;
    const float* src;
    __nv_bfloat16* dst;
    float* invp;
    if (warp < VROWS) {
        src = visual + (size_t)warp * DD;
        dst = g_xb + (size_t)warp * DD;
        invp = g_inv_nx + warp;
    } else {
        int r = warp - VROWS;
        src = text + (size_t)r * DD;
        dst = g_yb + (size_t)r * DD;
        invp = g_inv_ny + r;
    }
    const float4* s4 = (const float4*)src;
    uint2* d2 = (uint2*)dst;
    float ss = 0.0f;
#pragma unroll
    for (int i = 0; i < 8; ++i) {
        float4 v = __ldcs(&s4[lane + 32 * i]);
        ss += v.x * v.x + v.y * v.y + v.z * v.z + v.w * v.w;
        uint32_t lo = (uint32_t)__bfloat16_as_ushort(__float2bfloat16_rn(v.x))
                    | ((uint32_t)__bfloat16_as_ushort(__float2bfloat16_rn(v.y)) << 16);
        uint32_t hi = (uint32_t)__bfloat16_as_ushort(__float2bfloat16_rn(v.z))
                    | ((uint32_t)__bfloat16_as_ushort(__float2bfloat16_rn(v.w)) << 16);
        d2[lane + 32 * i] = make_uint2(lo, hi);
    }
    ss = warp_sum(ss);
    if (lane == 0) *invp = rsqrtf(ss + 1e-12f);
}

// ---------------- kernel 2: HMMA bf16 GEMM, 3-stage cp.async pipeline --------
#define ASTG 16384
#define BSTG 8192
__global__ void __launch_bounds__(256) gemm_expK_kernel() {
    extern __shared__ __align__(16) char dsm[];
    uint32_t SBASE = (uint32_t)__cvta_generic_to_shared(dsm);
    uint32_t SA = SBASE;                 // 3 x 16384
    uint32_t SB = SBASE + 3 * ASTG;      // 3 x 8192

    int tid = threadIdx.x, wid = tid >> 5, lane = tid & 31;
    int nt = blockIdx.x, mt = blockIdx.y, b = blockIdx.z;
    int wm = wid & 3, wn = wid >> 2;

    const __nv_bfloat16* Abase = g_yb + ((size_t)(b * MM + mt * 128)) * DD;
    const __nv_bfloat16* Bbase = g_xb + ((size_t)(b * NN + nt * 64)) * DD;

    float acc[2][4][4];
#pragma unroll
    for (int i = 0; i < 2; ++i)
#pragma unroll
        for (int j = 0; j < 4; ++j)
#pragma unroll
            for (int k = 0; k < 4; ++k) acc[i][j][k] = 0.0f;

    int a_row0 = wm * 32 + ((lane >> 3) & 1) * 8 + (lane & 7);
    int a_chunk_sel = (lane >> 4);
    int b_row0 = wn * 32 + (lane >> 4) * 8 + (lane & 7);
    int b_chunk_sel = ((lane >> 3) & 1);

    int arow[4], acol[4], brow[2], bcol[2];
    uint32_t aoff[4], boff[2];
#pragma unroll
    for (int q = 0; q < 4; ++q) {
        int c = tid + 256 * q;
        arow[q] = c >> 3; acol[q] = c & 7;
        aoff[q] = arow[q] * 128 + ((acol[q] ^ (arow[q] & 7)) * 16);
    }
#pragma unroll
    for (int q = 0; q < 2; ++q) {
        int c = tid + 256 * q;
        brow[q] = c >> 3; bcol[q] = c & 7;
        boff[q] = brow[q] * 128 + ((bcol[q] ^ (brow[q] & 7)) * 16);
    }

#define ISSUE(s)                                                               \
    do {                                                                       \
        int st_ = (s) % 3;                                                     \
        int kb_ = (s) * 64;                                                    \
        uint32_t ab_ = SA + st_ * ASTG, bb_ = SB + st_ * BSTG;                 \
        _Pragma("unroll")                                                      \
        for (int q = 0; q < 4; ++q)                                            \
            cp16(ab_ + aoff[q], Abase + (size_t)arow[q] * DD + kb_ + acol[q] * 8); \
        _Pragma("unroll")                                                      \
        for (int q = 0; q < 2; ++q)                                            \
            cp16(bb_ + boff[q], Bbase + (size_t)brow[q] * DD + kb_ + bcol[q] * 8); \
        asm volatile("cp.async.commit_group;" ::: "memory");                   \
    } while (0)

    ISSUE(0);
    ISSUE(1);

    for (int s = 0; s < 16; ++s) {
        if (s == 15)
            asm volatile("cp.async.wait_group 0;" ::: "memory");
        else
            asm volatile("cp.async.wait_group 1;" ::: "memory");
        __syncthreads();
        if (s + 2 < 16) ISSUE(s + 2);

        uint32_t SAc = SA + (s % 3) * ASTG;
        uint32_t SBc = SB + (s % 3) * BSTG;
#pragma unroll
        for (int kk = 0; kk < 4; ++kk) {
            uint32_t a0[4], a1[4], bA[4], bB[4];
            {
                int row = a_row0;
                int ch = kk * 2 + a_chunk_sel;
                ldsm4(a0, SAc + row * 128 + ((ch ^ (row & 7)) * 16));
                row = a_row0 + 16;
                ldsm4(a1, SAc + row * 128 + ((ch ^ (row & 7)) * 16));
            }
            {
                int row = b_row0;
                int ch = kk * 2 + b_chunk_sel;
                ldsm4(bA, SBc + row * 128 + ((ch ^ (row & 7)) * 16));
                row = b_row0 + 16;
                ldsm4(bB, SBc + row * 128 + ((ch ^ (row & 7)) * 16));
            }
            mma16816(acc[0][0], a0, bA + 0);
            mma16816(acc[0][1], a0, bA + 2);
            mma16816(acc[0][2], a0, bB + 0);
            mma16816(acc[0][3], a0, bB + 2);
            mma16816(acc[1][0], a1, bA + 0);
            mma16816(acc[1][1], a1, bA + 2);
            mma16816(acc[1][2], a1, bB + 0);
            mma16816(acc[1][3], a1, bB + 2);
        }
    }

    // epilogue: scale by inv-norms, exp((cos-1)*10), write g_K
    int mrow_base = mt * 128 + wm * 32 + (lane >> 2);
    int ncol_base = nt * 64 + wn * 32 + (lane & 3) * 2;
    const float* invx = g_inv_nx + b * NN;
    const float* invy = g_inv_ny + b * MM;
#pragma unroll
    for (int mi = 0; mi < 2; ++mi) {
#pragma unroll
        for (int half = 0; half < 2; ++half) {
            int m = mrow_base + mi * 16 + half * 8;
            float invm = invy[m];
            float* out = g_K + ((size_t)(b * MM + m)) * NN;
#pragma unroll
            for (int ni = 0; ni < 4; ++ni) {
                int n = ncol_base + ni * 8;
                float c0 = acc[mi][ni][half * 2 + 0];
                float c1 = acc[mi][ni][half * 2 + 1];
                float s0 = c0 * invm * invx[n];
                float s1 = c1 * invm * invx[n + 1];
                float2 e;
                e.x = __expf((s0 - 1.0f) * 10.0f);
                e.y = __expf((s1 - 1.0f) * 10.0f);
                *(float2*)(out + n) = e;
            }
        }
    }
}

// ---------------- kernel 3: Sinkhorn + teacher finalize (cluster per batch) ----
__global__ void __cluster_dims__(8, 1, 1) __launch_bounds__(256)
sinkhorn_kernel(const float* __restrict__ mask) {
    __shared__ float vsm[NN];
    __shared__ float usm[32];
    __shared__ float masksm[32];
    __shared__ float nusm[32];
    __shared__ float red[8];
    int tid = threadIdx.x;
    int b = blockIdx.x >> 3;
    int rank = blockIdx.x & 7;
    int wid = tid >> 5, lane = tid & 31;
    const int row0 = rank * 32;

    float mv = mask[b * MM + tid];
    float msum = block_sum256(mv, red);
    if (tid < 32) {
        float mk = mask[b * MM + row0 + tid];
        masksm[tid] = mk;
        nusm[tid] = mk / (msum + EPSF);
    }
    __syncthreads();

    float* Kbase = g_K + ((size_t)(b * MM + row0)) * NN;

    for (int it = 0; it < 5; ++it) {
        if (it == 0) {
            for (int j = tid; j < NN; j += 256) vsm[j] = 1.0f;
        } else {
            const float (*vp)[BB * NN] = g_vpart[(it - 1) & 1];
            for (int j = tid; j < NN; j += 256) {
                float s = 0.0f;
#pragma unroll
                for (int r = 0; r < 8; ++r) s += __ldcg(&vp[r][b * NN + j]);
                vsm[j] = __powf(MU_C / (s + EPSF), FI_C);
            }
        }
        __syncthreads();

#pragma unroll
        for (int r = 0; r < 4; ++r) {
            int rl = wid * 4 + r;
            const float* Kr = Kbase + (size_t)rl * NN;
            float acc = 0.0f;
#pragma unroll
            for (int i = 0; i < 18; ++i) {
                int j = lane + 32 * i;
                acc += Kr[j] * vsm[j];
            }
            acc = warp_sum(acc);
            if (lane == 0) usm[rl] = __powf(nusm[rl] / (acc + EPSF), FI_C);
        }
        __syncthreads();

        float a0 = 0.0f, a1 = 0.0f, a2 = 0.0f;
#pragma unroll 4
        for (int r = 0; r < 32; ++r) {
            const float* Kr = Kbase + (size_t)r * NN;
            float ur = usm[r];
            a0 += Kr[tid] * ur;
            a1 += Kr[tid + 256] * ur;
            if (tid < 64) a2 += Kr[tid + 512] * ur;
        }
        float* vp = g_vpart[it & 1][rank] + b * NN;
        vp[tid] = a0;
        vp[tid + 256] = a1;
        if (tid < 64) vp[tid + 512] = a2;
        __threadfence();
        cluster_sync();
    }

    {
        const float (*vp)[BB * NN] = g_vpart[0];
        for (int j = tid; j < NN; j += 256) {
            float s = 0.0f;
#pragma unroll
            for (int r = 0; r < 8; ++r) s += __ldcg(&vp[r][b * NN + j]);
            vsm[j] = __powf(MU_C / (s + EPSF), FI_C);
        }
    }
    __syncthreads();
#pragma unroll
    for (int r = 0; r < 4; ++r) {
        int rl = wid * 4 + r;
        float* Kr = Kbase + (size_t)rl * NN;
        float u = usm[rl];
        float pj[18];
        float rs = 0.0f;
#pragma unroll
        for (int i = 0; i < 18; ++i) {
            int j = lane + 32 * i;
            float p = u * Kr[j] * vsm[j];
            pj[i] = p;
            rs += p;
        }
        rs = warp_sum(rs);
        float scale = masksm[rl] / (rs + EPSF);
#pragma unroll
        for (int i = 0; i < 18; ++i) {
            int j = lane + 32 * i;
            Kr[j] = pj[i] * scale;
        }
    }
}

// ---------------- logsum: LS[b,m,j] = sum_h log(student + eps) ----------------
// Runs on a forked stream, concurrent with GEMM + Sinkhorn.
__global__ void __launch_bounds__(288) logsum_kernel(const float* __restrict__ student) {
    int blk = blockIdx.x, tid = threadIdx.x;
    int b = blk >> 8, m = blk & 255;
    const float* sbase = student + ((size_t)(b * HH) * MM + m) * NN;
    float2 sv[HH];
#pragma unroll
    for (int h = 0; h < HH; ++h)
        sv[h] = __ldcs((const float2*)(sbase + (size_t)h * MM * NN) + tid);
    float2 r = make_float2(0.0f, 0.0f);
#pragma unroll
    for (int h = 0; h < HH; ++h) {
        r.x += __logf(sv[h].x + EPSF);
        r.y += __logf(sv[h].y + EPSF);
    }
    ((float2*)(g_LS + (size_t)blk * NN))[tid] = r;
}

// ---------------- dot: sum P * LS + fused deterministic final reduce ----------
__global__ void __launch_bounds__(288) dot_kernel(float* __restrict__ out) {
    __shared__ float red[9];
    __shared__ bool last;
    int blk = blockIdx.x, tid = threadIdx.x;
    const float2* P = (const float2*)(g_K + (size_t)blk * NN);
    const float2* L = (const float2*)(g_LS + (size_t)blk * NN);
    float2 p = P[tid], l = L[tid];
    float acc = p.x * l.x + p.y * l.y;
    float tot = block_sum288(acc, red);
    if (tid == 0) {
        g_partial[blk] = tot;
        __threadfence();
        unsigned t = atomicAdd(&g_done, 1u);
        last = (t == (unsigned)(BB * MM - 1));
    }
    __syncthreads();
    if (last) {
        if (tid == 0) g_done = 0;  // reset for next graph replay
        float s = 0.0f;
        for (int i = tid; i < BB * MM; i += 288) s += g_partial[i];
        float t2 = block_sum288(s, red);
        if (tid == 0) out[0] = -t2 * (1.0f / (float)(BB * HH * MM));
    }
}

// ---------------- launch ----------------
extern "C" void kernel_launch(void* const* d_in, const int* in_sizes, int n_in,
                              void* d_out, int out_size) {
    const float *student = nullptr, *visual = nullptr, *text = nullptr, *mask = nullptr;
    for (int i = 0; i < n_in; ++i) {
        long sz = in_sizes[i];
        if (sz == (long)BB * HH * MM * NN) student = (const float*)d_in[i];
        else if (sz == (long)BB * NN * DD) visual = (const float*)d_in[i];
        else if (sz == (long)BB * MM * DD) text = (const float*)d_in[i];
        else if (sz == (long)BB * MM) mask = (const float*)d_in[i];
    }
    float* out = (float*)d_out;

    static cudaStream_t s2;
    static cudaEvent_t evA, evB;
    static bool init_done = false;
    if (!init_done) {
        cudaFuncSetAttribute(gemm_expK_kernel,
                             cudaFuncAttributeMaxDynamicSharedMemorySize,
                             3 * (ASTG + BSTG));
        cudaStreamCreateWithFlags(&s2, cudaStreamNonBlocking);
        cudaEventCreateWithFlags(&evA, cudaEventDisableTiming);
        cudaEventCreateWithFlags(&evB, cudaEventDisableTiming);
        init_done = true;
    }

    // stream 0: prep -> gemm -> sinkhorn -> dot
    // stream s2: logsum (student stream), forked after prep, joined before dot
    prep_kernel<<<(BB * NN + BB * MM) / 8, 256>>>(visual, text);
    cudaEventRecord(evA, 0);
    cudaStreamWaitEvent(s2, evA, 0);
    logsum_kernel<<<BB * MM, 288, 0, s2>>>(student);
    gemm_expK_kernel<<<dim3(NN / 64, MM / 128, BB), 256, 3 * (ASTG + BSTG)>>>();
    sinkhorn_kernel<<<128, 256>>>(mask);
    cudaEventRecord(evB, s2);
    cudaStreamWaitEvent(0, evB, 0);
    dot_kernel<<<BB * MM, 288>>>(out);
}

// round 9
// speedup vs baseline: 1.0630x; 1.0630x over previous
#include <cuda_runtime.h>
#include <cuda_bf16.h>
#include <cstdint>

// Problem constants: B=16, H=16, M=256, N=576, D=1024
#define BB 16
#define HH 16
#define MM 256
#define NN 576
#define DD 1024

#define EPSF 1e-8f
#define MU_C (1.0f / 576.0f)
#define FI_C (1.0f / 1.1f)

// ---------------- device scratch ----------------
__device__ __nv_bfloat16 g_xb[BB * NN * DD];   // visual feats bf16 (raw)
__device__ __nv_bfloat16 g_yb[BB * MM * DD];   // text feats bf16 (raw)
__device__ float g_inv_nx[BB * NN];
__device__ float g_inv_ny[BB * MM];
__device__ float g_K[BB * MM * NN];            // K, then overwritten with P*mask
__device__ float g_LS[BB * MM * NN];           // sum_h log(student)
__device__ float g_vpart[2][8][BB * NN];       // per-rank partial Ktu (parity buffered)
__device__ float g_partial[BB * MM];
__device__ unsigned g_done;

// ---------------- helpers ----------------
__device__ __forceinline__ float warp_sum(float v) {
#pragma unroll
    for (int o = 16; o; o >>= 1) v += __shfl_xor_sync(0xffffffffu, v, o);
    return v;
}

__device__ __forceinline__ float block_sum512(float v, volatile float* red) {
    int tid = threadIdx.x;
    float w = warp_sum(v);
    if ((tid & 31) == 0) red[tid >> 5] = w;
    __syncthreads();
    if (tid < 32) {
        float r = (tid < 16) ? red[tid] : 0.0f;
        r = warp_sum(r);
        if (tid == 0) red[0] = r;
    }
    __syncthreads();
    float out = red[0];
    __syncthreads();
    return out;
}

__device__ __forceinline__ float block_sum288(float v, volatile float* red) {
    int tid = threadIdx.x;
    float w = warp_sum(v);
    if ((tid & 31) == 0) red[tid >> 5] = w;
    __syncthreads();
    if (tid < 32) {
        float r = (tid < 9) ? red[tid] : 0.0f;
        r = warp_sum(r);
        if (tid == 0) red[0] = r;
    }
    __syncthreads();
    return red[0];
}

__device__ __forceinline__ void cluster_sync() {
    asm volatile("barrier.cluster.arrive.aligned;" ::: "memory");
    asm volatile("barrier.cluster.wait.aligned;" ::: "memory");
}

__device__ __forceinline__ void ldsm4(uint32_t* r, uint32_t addr) {
    asm volatile("ldmatrix.sync.aligned.m8n8.x4.shared.b16 {%0,%1,%2,%3}, [%4];"
                 : "=r"(r[0]), "=r"(r[1]), "=r"(r[2]), "=r"(r[3]) : "r"(addr));
}

__device__ __forceinline__ void mma16816(float* c, const uint32_t* a, const uint32_t* b) {
    asm volatile(
        "mma.sync.aligned.m16n8k16.row.col.f32.bf16.bf16.f32 "
        "{%0,%1,%2,%3}, {%4,%5,%6,%7}, {%8,%9}, {%0,%1,%2,%3};"
        : "+f"(c[0]), "+f"(c[1]), "+f"(c[2]), "+f"(c[3])
        : "r"(a[0]), "r"(a[1]), "r"(a[2]), "r"(a[3]), "r"(b[0]), "r"(b[1]));
}

__device__ __forceinline__ void cp16(uint32_t dst, const void* src) {
    asm volatile("cp.async.cg.shared.global [%0], [%1], 16;" :: "r"(dst), "l"(src));
}

// ---------------- kernel 1: norms + bf16 conversion ----------------
__global__ void __launch_bounds__(256) prep_kernel(const float* __restrict__ visual,
                                                   const float* __restrict__ text) {
    int warp = blockIdx.x * 8 + (threadIdx.x >> 5);
    int lane = threadIdx.x & 31;
    const int VROWS = BB * NN;
    const float* src;
    __nv_bfloat16* dst;
    float* invp;
    if (warp < VROWS) {
        src = visual + (size_t)warp * DD;
        dst = g_xb + (size_t)warp * DD;
        invp = g_inv_nx + warp;
    } else {
        int r = warp - VROWS;
        src = text + (size_t)r * DD;
        dst = g_yb + (size_t)r * DD;
        invp = g_inv_ny + r;
    }
    const float4* s4 = (const float4*)src;
    uint2* d2 = (uint2*)dst;
    float ss = 0.0f;
#pragma unroll
    for (int i = 0; i < 8; ++i) {
        float4 v = __ldcs(&s4[lane + 32 * i]);
        ss += v.x * v.x + v.y * v.y + v.z * v.z + v.w * v.w;
        uint32_t lo = (uint32_t)__bfloat16_as_ushort(__float2bfloat16_rn(v.x))
                    | ((uint32_t)__bfloat16_as_ushort(__float2bfloat16_rn(v.y)) << 16);
        uint32_t hi = (uint32_t)__bfloat16_as_ushort(__float2bfloat16_rn(v.z))
                    | ((uint32_t)__bfloat16_as_ushort(__float2bfloat16_rn(v.w)) << 16);
        d2[lane + 32 * i] = make_uint2(lo, hi);
    }
    ss = warp_sum(ss);
    if (lane == 0) *invp = rsqrtf(ss + 1e-12f);
}

// ---------------- kernel 2: HMMA bf16 GEMM, 3-stage cp.async pipeline --------
#define ASTG 16384
#define BSTG 8192
__global__ void __launch_bounds__(256) gemm_expK_kernel() {
    extern __shared__ __align__(16) char dsm[];
    uint32_t SBASE = (uint32_t)__cvta_generic_to_shared(dsm);
    uint32_t SA = SBASE;                 // 3 x 16384
    uint32_t SB = SBASE + 3 * ASTG;      // 3 x 8192

    int tid = threadIdx.x, wid = tid >> 5, lane = tid & 31;
    int nt = blockIdx.x, mt = blockIdx.y, b = blockIdx.z;
    int wm = wid & 3, wn = wid >> 2;

    const __nv_bfloat16* Abase = g_yb + ((size_t)(b * MM + mt * 128)) * DD;
    const __nv_bfloat16* Bbase = g_xb + ((size_t)(b * NN + nt * 64)) * DD;

    float acc[2][4][4];
#pragma unroll
    for (int i = 0; i < 2; ++i)
#pragma unroll
        for (int j = 0; j < 4; ++j)
#pragma unroll
            for (int k = 0; k < 4; ++k) acc[i][j][k] = 0.0f;

    int a_row0 = wm * 32 + ((lane >> 3) & 1) * 8 + (lane & 7);
    int a_chunk_sel = (lane >> 4);
    int b_row0 = wn * 32 + (lane >> 4) * 8 + (lane & 7);
    int b_chunk_sel = ((lane >> 3) & 1);

    int arow[4], acol[4], brow[2], bcol[2];
    uint32_t aoff[4], boff[2];
#pragma unroll
    for (int q = 0; q < 4; ++q) {
        int c = tid + 256 * q;
        arow[q] = c >> 3; acol[q] = c & 7;
        aoff[q] = arow[q] * 128 + ((acol[q] ^ (arow[q] & 7)) * 16);
    }
#pragma unroll
    for (int q = 0; q < 2; ++q) {
        int c = tid + 256 * q;
        brow[q] = c >> 3; bcol[q] = c & 7;
        boff[q] = brow[q] * 128 + ((bcol[q] ^ (brow[q] & 7)) * 16);
    }

#define ISSUE(s)                                                               \
    do {                                                                       \
        int st_ = (s) % 3;                                                     \
        int kb_ = (s) * 64;                                                    \
        uint32_t ab_ = SA + st_ * ASTG, bb_ = SB + st_ * BSTG;                 \
        _Pragma("unroll")                                                      \
        for (int q = 0; q < 4; ++q)                                            \
            cp16(ab_ + aoff[q], Abase + (size_t)arow[q] * DD + kb_ + acol[q] * 8); \
        _Pragma("unroll")                                                      \
        for (int q = 0; q < 2; ++q)                                            \
            cp16(bb_ + boff[q], Bbase + (size_t)brow[q] * DD + kb_ + bcol[q] * 8); \
        asm volatile("cp.async.commit_group;" ::: "memory");                   \
    } while (0)

    ISSUE(0);
    ISSUE(1);

    for (int s = 0; s < 16; ++s) {
        if (s == 15)
            asm volatile("cp.async.wait_group 0;" ::: "memory");
        else
            asm volatile("cp.async.wait_group 1;" ::: "memory");
        __syncthreads();
        if (s + 2 < 16) ISSUE(s + 2);

        uint32_t SAc = SA + (s % 3) * ASTG;
        uint32_t SBc = SB + (s % 3) * BSTG;
#pragma unroll
        for (int kk = 0; kk < 4; ++kk) {
            uint32_t a0[4], a1[4], bA[4], bB[4];
            {
                int row = a_row0;
                int ch = kk * 2 + a_chunk_sel;
                ldsm4(a0, SAc + row * 128 + ((ch ^ (row & 7)) * 16));
                row = a_row0 + 16;
                ldsm4(a1, SAc + row * 128 + ((ch ^ (row & 7)) * 16));
            }
            {
                int row = b_row0;
                int ch = kk * 2 + b_chunk_sel;
                ldsm4(bA, SBc + row * 128 + ((ch ^ (row & 7)) * 16));
                row = b_row0 + 16;
                ldsm4(bB, SBc + row * 128 + ((ch ^ (row & 7)) * 16));
            }
            mma16816(acc[0][0], a0, bA + 0);
            mma16816(acc[0][1], a0, bA + 2);
            mma16816(acc[0][2], a0, bB + 0);
            mma16816(acc[0][3], a0, bB + 2);
            mma16816(acc[1][0], a1, bA + 0);
            mma16816(acc[1][1], a1, bA + 2);
            mma16816(acc[1][2], a1, bB + 0);
            mma16816(acc[1][3], a1, bB + 2);
        }
    }

    // epilogue: scale by inv-norms, exp((cos-1)*10), write g_K
    int mrow_base = mt * 128 + wm * 32 + (lane >> 2);
    int ncol_base = nt * 64 + wn * 32 + (lane & 3) * 2;
    const float* invx = g_inv_nx + b * NN;
    const float* invy = g_inv_ny + b * MM;
#pragma unroll
    for (int mi = 0; mi < 2; ++mi) {
#pragma unroll
        for (int half = 0; half < 2; ++half) {
            int m = mrow_base + mi * 16 + half * 8;
            float invm = invy[m];
            float* out = g_K + ((size_t)(b * MM + m)) * NN;
#pragma unroll
            for (int ni = 0; ni < 4; ++ni) {
                int n = ncol_base + ni * 8;
                float c0 = acc[mi][ni][half * 2 + 0];
                float c1 = acc[mi][ni][half * 2 + 1];
                float s0 = c0 * invm * invx[n];
                float s1 = c1 * invm * invx[n + 1];
                float2 e;
                e.x = __expf((s0 - 1.0f) * 10.0f);
                e.y = __expf((s1 - 1.0f) * 10.0f);
                *(float2*)(out + n) = e;
            }
        }
    }
}

// ---------------- kernel 3: Sinkhorn + teacher finalize (cluster per batch) ----
// grid = 128 CTAs (16 clusters x 8) x 512 threads. CTA owns 32 K-rows.
// Phase A: 16 warps x 2 rows, interleaved load chains. Phase B: 576 cols over
// 512 threads. One cluster sync per iteration, no atomics.
__global__ void __cluster_dims__(8, 1, 1) __launch_bounds__(512)
sinkhorn_kernel(const float* __restrict__ mask) {
    __shared__ float vsm[NN];
    __shared__ float usm[32];
    __shared__ float masksm[32];
    __shared__ float nusm[32];
    __shared__ float red[16];
    int tid = threadIdx.x;
    int b = blockIdx.x >> 3;
    int rank = blockIdx.x & 7;
    int wid = tid >> 5, lane = tid & 31;
    const int row0 = rank * 32;

    float mv = (tid < MM) ? mask[b * MM + tid] : 0.0f;
    float msum = block_sum512(mv, red);
    if (tid < 32) {
        float mk = mask[b * MM + row0 + tid];
        masksm[tid] = mk;
        nusm[tid] = mk / (msum + EPSF);
    }
    __syncthreads();

    float* Kbase = g_K + ((size_t)(b * MM + row0)) * NN;
    const int rl0 = wid * 2, rl1 = wid * 2 + 1;
    const float* K0 = Kbase + (size_t)rl0 * NN;
    const float* K1 = Kbase + (size_t)rl1 * NN;

    for (int it = 0; it < 5; ++it) {
        // ---- build v in smem from previous iteration's partials ----
        if (it == 0) {
            for (int j = tid; j < NN; j += 512) vsm[j] = 1.0f;
        } else {
            const float (*vp)[BB * NN] = g_vpart[(it - 1) & 1];
            for (int j = tid; j < NN; j += 512) {
                float s = 0.0f;
#pragma unroll
                for (int r = 0; r < 8; ++r) s += __ldcg(&vp[r][b * NN + j]);
                vsm[j] = __powf(MU_C / (s + EPSF), FI_C);
            }
        }
        __syncthreads();

        // ---- phase A: u for 2 rows per warp, interleaved chains ----
        {
            float acc0 = 0.0f, acc1 = 0.0f;
#pragma unroll
            for (int i = 0; i < 18; ++i) {
                int j = lane + 32 * i;
                float vv = vsm[j];
                acc0 += K0[j] * vv;
                acc1 += K1[j] * vv;
            }
            acc0 = warp_sum(acc0);
            acc1 = warp_sum(acc1);
            if (lane == 0) {
                usm[rl0] = __powf(nusm[rl0] / (acc0 + EPSF), FI_C);
                usm[rl1] = __powf(nusm[rl1] / (acc1 + EPSF), FI_C);
            }
        }
        __syncthreads();

        // ---- phase B: partial Ktu over own rows, 576 cols / 512 threads ----
        float a0 = 0.0f, a1 = 0.0f;
#pragma unroll 8
        for (int r = 0; r < 32; ++r) {
            const float* Kr = Kbase + (size_t)r * NN;
            float ur = usm[r];
            a0 += Kr[tid] * ur;
            if (tid < 64) a1 += Kr[tid + 512] * ur;
        }
        float* vp = g_vpart[it & 1][rank] + b * NN;
        vp[tid] = a0;
        if (tid < 64) vp[tid + 512] = a1;
        __threadfence();
        cluster_sync();
    }

    // ---- tail: final v, then P finalize (2 rows per warp) ----
    {
        const float (*vp)[BB * NN] = g_vpart[0];
        for (int j = tid; j < NN; j += 512) {
            float s = 0.0f;
#pragma unroll
            for (int r = 0; r < 8; ++r) s += __ldcg(&vp[r][b * NN + j]);
            vsm[j] = __powf(MU_C / (s + EPSF), FI_C);
        }
    }
    __syncthreads();
#pragma unroll
    for (int r = 0; r < 2; ++r) {
        int rl = wid * 2 + r;
        float* Kr = Kbase + (size_t)rl * NN;
        float u = usm[rl];
        float pj[18];
        float rs = 0.0f;
#pragma unroll
        for (int i = 0; i < 18; ++i) {
            int j = lane + 32 * i;
            float p = u * Kr[j] * vsm[j];
            pj[i] = p;
            rs += p;
        }
        rs = warp_sum(rs);
        float scale = masksm[rl] / (rs + EPSF);
#pragma unroll
        for (int i = 0; i < 18; ++i) {
            int j = lane + 32 * i;
            Kr[j] = pj[i] * scale;
        }
    }
}

// ---------------- logsum: LS[b,m,j] = sum_h log(student + eps) ----------------
// Forked at capture start; overlaps prep + GEMM + Sinkhorn.
__global__ void __launch_bounds__(288) logsum_kernel(const float* __restrict__ student) {
    int blk = blockIdx.x, tid = threadIdx.x;
    int b = blk >> 8, m = blk & 255;
    const float* sbase = student + ((size_t)(b * HH) * MM + m) * NN;
    float2 sv[HH];
#pragma unroll
    for (int h = 0; h < HH; ++h)
        sv[h] = __ldcs((const float2*)(sbase + (size_t)h * MM * NN) + tid);
    float2 r = make_float2(0.0f, 0.0f);
#pragma unroll
    for (int h = 0; h < HH; ++h) {
        r.x += __logf(sv[h].x + EPSF);
        r.y += __logf(sv[h].y + EPSF);
    }
    ((float2*)(g_LS + (size_t)blk * NN))[tid] = r;
}

// ---------------- dot: sum P * LS + fused deterministic final reduce ----------
__global__ void __launch_bounds__(288) dot_kernel(float* __restrict__ out) {
    __shared__ float red[9];
    __shared__ bool last;
    int blk = blockIdx.x, tid = threadIdx.x;
    const float2* P = (const float2*)(g_K + (size_t)blk * NN);
    const float2* L = (const float2*)(g_LS + (size_t)blk * NN);
    float2 p = P[tid], l = L[tid];
    float acc = p.x * l.x + p.y * l.y;
    float tot = block_sum288(acc, red);
    if (tid == 0) {
        g_partial[blk] = tot;
        __threadfence();
        unsigned t = atomicAdd(&g_done, 1u);
        last = (t == (unsigned)(BB * MM - 1));
    }
    __syncthreads();
    if (last) {
        if (tid == 0) g_done = 0;  // reset for next graph replay
        float s = 0.0f;
        for (int i = tid; i < BB * MM; i += 288) s += g_partial[i];
        float t2 = block_sum288(s, red);
        if (tid == 0) out[0] = -t2 * (1.0f / (float)(BB * HH * MM));
    }
}

// ---------------- launch ----------------
extern "C" void kernel_launch(void* const* d_in, const int* in_sizes, int n_in,
                              void* d_out, int out_size) {
    const float *student = nullptr, *visual = nullptr, *text = nullptr, *mask = nullptr;
    for (int i = 0; i < n_in; ++i) {
        long sz = in_sizes[i];
        if (sz == (long)BB * HH * MM * NN) student = (const float*)d_in[i];
        else if (sz == (long)BB * NN * DD) visual = (const float*)d_in[i];
        else if (sz == (long)BB * MM * DD) text = (const float*)d_in[i];
        else if (sz == (long)BB * MM) mask = (const float*)d_in[i];
    }
    float* out = (float*)d_out;

    static cudaStream_t s2;
    static cudaEvent_t evA, evB;
    static bool init_done = false;
    if (!init_done) {
        cudaFuncSetAttribute(gemm_expK_kernel,
                             cudaFuncAttributeMaxDynamicSharedMemorySize,
                             3 * (ASTG + BSTG));
        cudaStreamCreateWithFlags(&s2, cudaStreamNonBlocking);
        cudaEventCreateWithFlags(&evA, cudaEventDisableTiming);
        cudaEventCreateWithFlags(&evB, cudaEventDisableTiming);
        init_done = true;
    }

    // stream 0: prep -> gemm -> sinkhorn -> dot
    // stream s2: logsum (student only), forked at start, joined before dot
    cudaEventRecord(evA, 0);
    cudaStreamWaitEvent(s2, evA, 0);
    logsum_kernel<<<BB * MM, 288, 0, s2>>>(student);
    prep_kernel<<<(BB * NN + BB * MM) / 8, 256>>>(visual, text);
    gemm_expK_kernel<<<dim3(NN / 64, MM / 128, BB), 256, 3 * (ASTG + BSTG)>>>();
    sinkhorn_kernel<<<128, 512>>>(mask);
    cudaEventRecord(evB, s2);
    cudaStreamWaitEvent(0, evB, 0);
    dot_kernel<<<BB * MM, 288>>>(out);
}

// round 10
// speedup vs baseline: 1.0830x; 1.0188x over previous
#include <cuda_runtime.h>
#include <cuda_bf16.h>
#include <cstdint>

// Problem constants: B=16, H=16, M=256, N=576, D=1024
#define BB 16
#define HH 16
#define MM 256
#define NN 576
#define DD 1024

#define EPSF 1e-8f
#define MU_C (1.0f / 576.0f)
#define FI_C (1.0f / 1.1f)

// ---------------- device scratch ----------------
__device__ __nv_bfloat16 g_xb[BB * NN * DD];   // visual feats bf16 (raw)
__device__ __nv_bfloat16 g_yb[BB * MM * DD];   // text feats bf16 (raw)
__device__ float g_inv_nx[BB * NN];
__device__ float g_inv_ny[BB * MM];
__device__ float g_K[BB * MM * NN];            // K, then overwritten with P*mask
__device__ float g_LS[BB * MM * NN];           // sum_h log(student)
__device__ float g_vpart[2][8][BB * NN];       // per-rank partial Ktu (parity buffered)
__device__ float g_partial[BB * MM];
__device__ unsigned g_done;

// ---------------- helpers ----------------
__device__ __forceinline__ float warp_sum(float v) {
#pragma unroll
    for (int o = 16; o; o >>= 1) v += __shfl_xor_sync(0xffffffffu, v, o);
    return v;
}

__device__ __forceinline__ float block_sum512(float v, volatile float* red) {
    int tid = threadIdx.x;
    float w = warp_sum(v);
    if ((tid & 31) == 0) red[tid >> 5] = w;
    __syncthreads();
    if (tid < 32) {
        float r = (tid < 16) ? red[tid] : 0.0f;
        r = warp_sum(r);
        if (tid == 0) red[0] = r;
    }
    __syncthreads();
    float out = red[0];
    __syncthreads();
    return out;
}

__device__ __forceinline__ float block_sum288(float v, volatile float* red) {
    int tid = threadIdx.x;
    float w = warp_sum(v);
    if ((tid & 31) == 0) red[tid >> 5] = w;
    __syncthreads();
    if (tid < 32) {
        float r = (tid < 9) ? red[tid] : 0.0f;
        r = warp_sum(r);
        if (tid == 0) red[0] = r;
    }
    __syncthreads();
    return red[0];
}

__device__ __forceinline__ void cluster_sync() {
    asm volatile("barrier.cluster.arrive.aligned;" ::: "memory");
    asm volatile("barrier.cluster.wait.aligned;" ::: "memory");
}

__device__ __forceinline__ void ldsm4(uint32_t* r, uint32_t addr) {
    asm volatile("ldmatrix.sync.aligned.m8n8.x4.shared.b16 {%0,%1,%2,%3}, [%4];"
                 : "=r"(r[0]), "=r"(r[1]), "=r"(r[2]), "=r"(r[3]) : "r"(addr));
}

__device__ __forceinline__ void mma16816(float* c, const uint32_t* a, const uint32_t* b) {
    asm volatile(
        "mma.sync.aligned.m16n8k16.row.col.f32.bf16.bf16.f32 "
        "{%0,%1,%2,%3}, {%4,%5,%6,%7}, {%8,%9}, {%0,%1,%2,%3};"
        : "+f"(c[0]), "+f"(c[1]), "+f"(c[2]), "+f"(c[3])
        : "r"(a[0]), "r"(a[1]), "r"(a[2]), "r"(a[3]), "r"(b[0]), "r"(b[1]));
}

__device__ __forceinline__ void cp16(uint32_t dst, const void* src) {
    asm volatile("cp.async.cg.shared.global [%0], [%1], 16;" :: "r"(dst), "l"(src));
}

// ---------------- kernel 1: norms + bf16 conversion ----------------
__global__ void __launch_bounds__(256) prep_kernel(const float* __restrict__ visual,
                                                   const float* __restrict__ text) {
    int warp = blockIdx.x * 8 + (threadIdx.x >> 5);
    int lane = threadIdx.x & 31;
    const int VROWS = BB * NN;
    const float* src;
    __nv_bfloat16* dst;
    float* invp;
    if (warp < VROWS) {
        src = visual + (size_t)warp * DD;
        dst = g_xb + (size_t)warp * DD;
        invp = g_inv_nx + warp;
    } else {
        int r = warp - VROWS;
        src = text + (size_t)r * DD;
        dst = g_yb + (size_t)r * DD;
        invp = g_inv_ny + r;
    }
    const float4* s4 = (const float4*)src;
    uint2* d2 = (uint2*)dst;
    float ss = 0.0f;
#pragma unroll
    for (int i = 0; i < 8; ++i) {
        float4 v = __ldcs(&s4[lane + 32 * i]);
        ss += v.x * v.x + v.y * v.y + v.z * v.z + v.w * v.w;
        uint32_t lo = (uint32_t)__bfloat16_as_ushort(__float2bfloat16_rn(v.x))
                    | ((uint32_t)__bfloat16_as_ushort(__float2bfloat16_rn(v.y)) << 16);
        uint32_t hi = (uint32_t)__bfloat16_as_ushort(__float2bfloat16_rn(v.z))
                    | ((uint32_t)__bfloat16_as_ushort(__float2bfloat16_rn(v.w)) << 16);
        d2[lane + 32 * i] = make_uint2(lo, hi);
    }
    ss = warp_sum(ss);
    if (lane == 0) *invp = rsqrtf(ss + 1e-12f);
}

// ---------------- kernel 2: HMMA bf16 GEMM, 3-stage cp.async pipeline --------
#define ASTG 16384
#define BSTG 8192
__global__ void __launch_bounds__(256) gemm_expK_kernel() {
    extern __shared__ __align__(16) char dsm[];
    uint32_t SBASE = (uint32_t)__cvta_generic_to_shared(dsm);
    uint32_t SA = SBASE;                 // 3 x 16384
    uint32_t SB = SBASE + 3 * ASTG;      // 3 x 8192

    int tid = threadIdx.x, wid = tid >> 5, lane = tid & 31;
    int nt = blockIdx.x, mt = blockIdx.y, b = blockIdx.z;
    int wm = wid & 3, wn = wid >> 2;

    const __nv_bfloat16* Abase = g_yb + ((size_t)(b * MM + mt * 128)) * DD;
    const __nv_bfloat16* Bbase = g_xb + ((size_t)(b * NN + nt * 64)) * DD;

    float acc[2][4][4];
#pragma unroll
    for (int i = 0; i < 2; ++i)
#pragma unroll
        for (int j = 0; j < 4; ++j)
#pragma unroll
            for (int k = 0; k < 4; ++k) acc[i][j][k] = 0.0f;

    int a_row0 = wm * 32 + ((lane >> 3) & 1) * 8 + (lane & 7);
    int a_chunk_sel = (lane >> 4);
    int b_row0 = wn * 32 + (lane >> 4) * 8 + (lane & 7);
    int b_chunk_sel = ((lane >> 3) & 1);

    int arow[4], acol[4], brow[2], bcol[2];
    uint32_t aoff[4], boff[2];
#pragma unroll
    for (int q = 0; q < 4; ++q) {
        int c = tid + 256 * q;
        arow[q] = c >> 3; acol[q] = c & 7;
        aoff[q] = arow[q] * 128 + ((acol[q] ^ (arow[q] & 7)) * 16);
    }
#pragma unroll
    for (int q = 0; q < 2; ++q) {
        int c = tid + 256 * q;
        brow[q] = c >> 3; bcol[q] = c & 7;
        boff[q] = brow[q] * 128 + ((bcol[q] ^ (brow[q] & 7)) * 16);
    }

#define ISSUE(s)                                                               \
    do {                                                                       \
        int st_ = (s) % 3;                                                     \
        int kb_ = (s) * 64;                                                    \
        uint32_t ab_ = SA + st_ * ASTG, bb_ = SB + st_ * BSTG;                 \
        _Pragma("unroll")                                                      \
        for (int q = 0; q < 4; ++q)                                            \
            cp16(ab_ + aoff[q], Abase + (size_t)arow[q] * DD + kb_ + acol[q] * 8); \
        _Pragma("unroll")                                                      \
        for (int q = 0; q < 2; ++q)                                            \
            cp16(bb_ + boff[q], Bbase + (size_t)brow[q] * DD + kb_ + bcol[q] * 8); \
        asm volatile("cp.async.commit_group;" ::: "memory");                   \
    } while (0)

    ISSUE(0);
    ISSUE(1);

    for (int s = 0; s < 16; ++s) {
        if (s == 15)
            asm volatile("cp.async.wait_group 0;" ::: "memory");
        else
            asm volatile("cp.async.wait_group 1;" ::: "memory");
        __syncthreads();
        if (s + 2 < 16) ISSUE(s + 2);

        uint32_t SAc = SA + (s % 3) * ASTG;
        uint32_t SBc = SB + (s % 3) * BSTG;
#pragma unroll
        for (int kk = 0; kk < 4; ++kk) {
            uint32_t a0[4], a1[4], bA[4], bB[4];
            {
                int row = a_row0;
                int ch = kk * 2 + a_chunk_sel;
                ldsm4(a0, SAc + row * 128 + ((ch ^ (row & 7)) * 16));
                row = a_row0 + 16;
                ldsm4(a1, SAc + row * 128 + ((ch ^ (row & 7)) * 16));
            }
            {
                int row = b_row0;
                int ch = kk * 2 + b_chunk_sel;
                ldsm4(bA, SBc + row * 128 + ((ch ^ (row & 7)) * 16));
                row = b_row0 + 16;
                ldsm4(bB, SBc + row * 128 + ((ch ^ (row & 7)) * 16));
            }
            mma16816(acc[0][0], a0, bA + 0);
            mma16816(acc[0][1], a0, bA + 2);
            mma16816(acc[0][2], a0, bB + 0);
            mma16816(acc[0][3], a0, bB + 2);
            mma16816(acc[1][0], a1, bA + 0);
            mma16816(acc[1][1], a1, bA + 2);
            mma16816(acc[1][2], a1, bB + 0);
            mma16816(acc[1][3], a1, bB + 2);
        }
    }

    // epilogue: scale by inv-norms, exp((cos-1)*10), write g_K
    int mrow_base = mt * 128 + wm * 32 + (lane >> 2);
    int ncol_base = nt * 64 + wn * 32 + (lane & 3) * 2;
    const float* invx = g_inv_nx + b * NN;
    const float* invy = g_inv_ny + b * MM;
#pragma unroll
    for (int mi = 0; mi < 2; ++mi) {
#pragma unroll
        for (int half = 0; half < 2; ++half) {
            int m = mrow_base + mi * 16 + half * 8;
            float invm = invy[m];
            float* out = g_K + ((size_t)(b * MM + m)) * NN;
#pragma unroll
            for (int ni = 0; ni < 4; ++ni) {
                int n = ncol_base + ni * 8;
                float c0 = acc[mi][ni][half * 2 + 0];
                float c1 = acc[mi][ni][half * 2 + 1];
                float s0 = c0 * invm * invx[n];
                float s1 = c1 * invm * invx[n + 1];
                float2 e;
                e.x = __expf((s0 - 1.0f) * 10.0f);
                e.y = __expf((s1 - 1.0f) * 10.0f);
                *(float2*)(out + n) = e;
            }
        }
    }
}

// ---------------- kernel 3: Sinkhorn + teacher finalize (cluster per batch) ----
// grid = 128 CTAs (16 clusters x 8) x 512 threads. CTA's 32 K-rows (72 KB) are
// staged in DYNAMIC SHARED MEMORY so the L1D flush from cluster_sync / fences
// cannot evict them. All 11 sweeps run at LDS latency/bandwidth.
#define KSLICE (32 * NN)
__global__ void __cluster_dims__(8, 1, 1) __launch_bounds__(512)
sinkhorn_kernel(const float* __restrict__ mask) {
    extern __shared__ __align__(16) float sk[];   // [32][NN]
    __shared__ float vsm[NN];
    __shared__ float usm[32];
    __shared__ float masksm[32];
    __shared__ float nusm[32];
    __shared__ float red[16];
    int tid = threadIdx.x;
    int b = blockIdx.x >> 3;
    int rank = blockIdx.x & 7;
    int wid = tid >> 5, lane = tid & 31;
    const int row0 = rank * 32;

    float mv = (tid < MM) ? mask[b * MM + tid] : 0.0f;
    float msum = block_sum512(mv, red);
    if (tid < 32) {
        float mk = mask[b * MM + row0 + tid];
        masksm[tid] = mk;
        nusm[tid] = mk / (msum + EPSF);
    }

    float* Kbase = g_K + ((size_t)(b * MM + row0)) * NN;
    // stage K slice into smem (coalesced float4; 18432 f4 / 512 thr = 36 each)
    {
        const float4* src = (const float4*)Kbase;
        float4* dst = (float4*)sk;
#pragma unroll
        for (int i = 0; i < KSLICE / 4 / 512; ++i)
            dst[tid + 512 * i] = src[tid + 512 * i];
    }
    __syncthreads();

    const int rl0 = wid * 2, rl1 = wid * 2 + 1;
    const float* K0 = sk + rl0 * NN;
    const float* K1 = sk + rl1 * NN;

    for (int it = 0; it < 5; ++it) {
        // ---- build v in smem from previous iteration's partials ----
        if (it == 0) {
            for (int j = tid; j < NN; j += 512) vsm[j] = 1.0f;
        } else {
            const float (*vp)[BB * NN] = g_vpart[(it - 1) & 1];
            for (int j = tid; j < NN; j += 512) {
                float s = 0.0f;
#pragma unroll
                for (int r = 0; r < 8; ++r) s += __ldcg(&vp[r][b * NN + j]);
                vsm[j] = __powf(MU_C / (s + EPSF), FI_C);
            }
        }
        __syncthreads();

        // ---- phase A: u for 2 rows per warp (smem) ----
        {
            float acc0 = 0.0f, acc1 = 0.0f;
#pragma unroll
            for (int i = 0; i < 18; ++i) {
                int j = lane + 32 * i;
                float vv = vsm[j];
                acc0 += K0[j] * vv;
                acc1 += K1[j] * vv;
            }
            acc0 = warp_sum(acc0);
            acc1 = warp_sum(acc1);
            if (lane == 0) {
                usm[rl0] = __powf(nusm[rl0] / (acc0 + EPSF), FI_C);
                usm[rl1] = __powf(nusm[rl1] / (acc1 + EPSF), FI_C);
            }
        }
        __syncthreads();

        // ---- phase B: partial Ktu over own rows (smem), 576 cols / 512 thr ----
        float a0 = 0.0f, a1 = 0.0f;
#pragma unroll 8
        for (int r = 0; r < 32; ++r) {
            const float* Kr = sk + r * NN;
            float ur = usm[r];
            a0 += Kr[tid] * ur;
            if (tid < 64) a1 += Kr[tid + 512] * ur;
        }
        float* vp = g_vpart[it & 1][rank] + b * NN;
        vp[tid] = a0;
        if (tid < 64) vp[tid + 512] = a1;
        __threadfence();
        cluster_sync();
    }

    // ---- tail: final v, then P finalize (smem -> global) ----
    {
        const float (*vp)[BB * NN] = g_vpart[0];
        for (int j = tid; j < NN; j += 512) {
            float s = 0.0f;
#pragma unroll
            for (int r = 0; r < 8; ++r) s += __ldcg(&vp[r][b * NN + j]);
            vsm[j] = __powf(MU_C / (s + EPSF), FI_C);
        }
    }
    __syncthreads();
#pragma unroll
    for (int r = 0; r < 2; ++r) {
        int rl = wid * 2 + r;
        const float* Kr = sk + rl * NN;
        float* Kg = Kbase + (size_t)rl * NN;
        float u = usm[rl];
        float pj[18];
        float rs = 0.0f;
#pragma unroll
        for (int i = 0; i < 18; ++i) {
            int j = lane + 32 * i;
            float p = u * Kr[j] * vsm[j];
            pj[i] = p;
            rs += p;
        }
        rs = warp_sum(rs);
        float scale = masksm[rl] / (rs + EPSF);
#pragma unroll
        for (int i = 0; i < 18; ++i) {
            int j = lane + 32 * i;
            Kg[j] = pj[i] * scale;
        }
    }
}

// ---------------- logsum: LS[b,m,j] = sum_h log(student + eps) ----------------
// Forked at capture start; overlaps prep + GEMM + Sinkhorn.
__global__ void __launch_bounds__(288) logsum_kernel(const float* __restrict__ student) {
    int blk = blockIdx.x, tid = threadIdx.x;
    int b = blk >> 8, m = blk & 255;
    const float* sbase = student + ((size_t)(b * HH) * MM + m) * NN;
    float2 sv[HH];
#pragma unroll
    for (int h = 0; h < HH; ++h)
        sv[h] = __ldcs((const float2*)(sbase + (size_t)h * MM * NN) + tid);
    float2 r = make_float2(0.0f, 0.0f);
#pragma unroll
    for (int h = 0; h < HH; ++h) {
        r.x += __logf(sv[h].x + EPSF);
        r.y += __logf(sv[h].y + EPSF);
    }
    ((float2*)(g_LS + (size_t)blk * NN))[tid] = r;
}

// ---------------- dot: sum P * LS + fused deterministic final reduce ----------
__global__ void __launch_bounds__(288) dot_kernel(float* __restrict__ out) {
    __shared__ float red[9];
    __shared__ bool last;
    int blk = blockIdx.x, tid = threadIdx.x;
    const float2* P = (const float2*)(g_K + (size_t)blk * NN);
    const float2* L = (const float2*)(g_LS + (size_t)blk * NN);
    float2 p = P[tid], l = L[tid];
    float acc = p.x * l.x + p.y * l.y;
    float tot = block_sum288(acc, red);
    if (tid == 0) {
        g_partial[blk] = tot;
        __threadfence();
        unsigned t = atomicAdd(&g_done, 1u);
        last = (t == (unsigned)(BB * MM - 1));
    }
    __syncthreads();
    if (last) {
        if (tid == 0) g_done = 0;  // reset for next graph replay
        float s = 0.0f;
        for (int i = tid; i < BB * MM; i += 288) s += g_partial[i];
        float t2 = block_sum288(s, red);
        if (tid == 0) out[0] = -t2 * (1.0f / (float)(BB * HH * MM));
    }
}

// ---------------- launch ----------------
extern "C" void kernel_launch(void* const* d_in, const int* in_sizes, int n_in,
                              void* d_out, int out_size) {
    const float *student = nullptr, *visual = nullptr, *text = nullptr, *mask = nullptr;
    for (int i = 0; i < n_in; ++i) {
        long sz = in_sizes[i];
        if (sz == (long)BB * HH * MM * NN) student = (const float*)d_in[i];
        else if (sz == (long)BB * NN * DD) visual = (const float*)d_in[i];
        else if (sz == (long)BB * MM * DD) text = (const float*)d_in[i];
        else if (sz == (long)BB * MM) mask = (const float*)d_in[i];
    }
    float* out = (float*)d_out;

    static cudaStream_t s2;
    static cudaEvent_t evA, evB;
    static bool init_done = false;
    if (!init_done) {
        cudaFuncSetAttribute(gemm_expK_kernel,
                             cudaFuncAttributeMaxDynamicSharedMemorySize,
                             3 * (ASTG + BSTG));
        cudaFuncSetAttribute(sinkhorn_kernel,
                             cudaFuncAttributeMaxDynamicSharedMemorySize,
                             KSLICE * 4);
        cudaStreamCreateWithFlags(&s2, cudaStreamNonBlocking);
        cudaEventCreateWithFlags(&evA, cudaEventDisableTiming);
        cudaEventCreateWithFlags(&evB, cudaEventDisableTiming);
        init_done = true;
    }

    // stream 0: prep -> gemm -> sinkhorn -> dot
    // stream s2: logsum (student only), forked at start, joined before dot
    cudaEventRecord(evA, 0);
    cudaStreamWaitEvent(s2, evA, 0);
    logsum_kernel<<<BB * MM, 288, 0, s2>>>(student);
    prep_kernel<<<(BB * NN + BB * MM) / 8, 256>>>(visual, text);
    gemm_expK_kernel<<<dim3(NN / 64, MM / 128, BB), 256, 3 * (ASTG + BSTG)>>>();
    sinkhorn_kernel<<<128, 512, KSLICE * 4>>>(mask);
    cudaEventRecord(evB, s2);
    cudaStreamWaitEvent(0, evB, 0);
    dot_kernel<<<BB * MM, 288>>>(out);
}